// round 15
// baseline (speedup 1.0000x reference)
#include <cuda_runtime.h>
#include <cuda_fp16.h>
#include <math.h>
#include <stddef.h>
#include <stdint.h>

#define M_ROWS 32768      // B*HW
#define DM     256
#define C_IN   512
#define D_FF   1024
#define HW_N   4096
#define EPSF   1e-5f
typedef __half fp16;

// ---------------- scratch (static device arrays) ----------------
__device__ fp16  g_xT16 [(size_t)M_ROWS * C_IN];
__device__ fp16  g_src16[(size_t)M_ROWS * DM];
__device__ float g_q32  [(size_t)M_ROWS * DM];
__device__ fp16  g_q16  [(size_t)M_ROWS * DM];
__device__ fp16  g_qe16 [(size_t)HW_N * DM];
__device__ fp16  g_val16[(size_t)M_ROWS * DM];
__device__ fp16  g_samp16[(size_t)M_ROWS * DM];
__device__ fp16  g_tmp16[(size_t)M_ROWS * DM];
__device__ fp16  g_ffh16[(size_t)M_ROWS * D_FF];
__device__ float g_fa   [(size_t)M_ROWS * 96];
__device__ fp16  g_WinT [DM * C_IN];
__device__ fp16  g_WvT  [2 * DM * DM];
__device__ fp16  g_WoT  [2 * DM * DM];
__device__ fp16  g_W1T  [2 * D_FF * DM];
__device__ fp16  g_W2T  [2 * DM * D_FF];
__device__ fp16  g_faT  [2 * 96 * DM];
__device__ fp16  g_WoutT[C_IN * DM];
__device__ float g_fab[2 * 96];
__device__ float g_bn1s[DM], g_bn1t[DM];
__device__ float g_bn2s[C_IN], g_bn2t[C_IN];

// ---------------- helpers ----------------
__device__ __forceinline__ uint32_t smem_u32(const void* p) {
    uint32_t a;
    asm("{ .reg .u64 t; cvta.to.shared.u64 t, %1; cvt.u32.u64 %0, t; }" : "=r"(a) : "l"(p));
    return a;
}
__device__ __forceinline__ void cp16(uint32_t d, const void* s) {
    asm volatile("cp.async.cg.shared.global [%0], [%1], 16;" :: "r"(d), "l"(s));
}
__device__ __forceinline__ void cp16z(uint32_t d, const void* s) {
    asm volatile("cp.async.cg.shared.global [%0], [%1], 16, %2;" :: "r"(d), "l"(s), "r"(0));
}
__device__ __forceinline__ void cp_commit() {
    asm volatile("cp.async.commit_group;");
}
template <int N>
__device__ __forceinline__ void cp_wait() {
    asm volatile("cp.async.wait_group %0;" :: "n"(N));
}
__device__ __forceinline__ void ldsm4(uint32_t* r, uint32_t a) {
    asm volatile("ldmatrix.sync.aligned.m8n8.x4.shared.b16 {%0,%1,%2,%3}, [%4];"
                 : "=r"(r[0]), "=r"(r[1]), "=r"(r[2]), "=r"(r[3]) : "r"(a));
}
__device__ __forceinline__ void mma16816(float* c, const uint32_t* a, const uint32_t* b) {
    asm volatile(
        "mma.sync.aligned.m16n8k16.row.col.f32.f16.f16.f32 "
        "{%0,%1,%2,%3}, {%4,%5,%6,%7}, {%8,%9}, {%0,%1,%2,%3};"
        : "+f"(c[0]), "+f"(c[1]), "+f"(c[2]), "+f"(c[3])
        : "r"(a[0]), "r"(a[1]), "r"(a[2]), "r"(a[3]), "r"(b[0]), "r"(b[1]));
}

// ---------------- HMMA GEMM ----------------
// C(M,N) = epi( A(M,K) @ B^T ): single-pass fp16 A and B (W^T row-major N x K).
// 128x128 block tile, 128 threads (4 warps, 2x2 grid, 64x64 warp tile),
// BK=32, THREE-stage cp.async pipeline. 2 smem mats/stage (A, B).
// EPI 0: fp32 row-major (+bias). EPI 1: fp16 out (+bias/bn/relu). EPI 2: fp32 BCHW.
#define SM_STRIDE   80
#define SM_MAT      10240
#define SM_STAGE    20480
#define GEMM_SMEM_BYTES 66560   // max(3*SM_STAGE, 128*129*4)

__device__ __forceinline__ void gemm_load_stage(
    uint32_t sb, int tid, int rowBase, int colBase, int N, int K, int kc,
    const fp16* __restrict__ A, const fp16* __restrict__ B)
{
    int k0 = kc * 32;
#pragma unroll
    for (int j = 0; j < 4; j++) {
        int g = tid + j * 128;
        int row = g >> 2, k4 = g & 3;   // 512 quads: 128 rows x 4 k-groups
        uint32_t dst = sb + row * SM_STRIDE + k4 * 16;
        size_t ga = (size_t)(rowBase + row) * K + k0 + k4 * 8;
        cp16(dst, A + ga);
        int n = colBase + row;
        if (n < N) {
            size_t gb = (size_t)n * K + k0 + k4 * 8;
            cp16(dst + SM_MAT, B + gb);
        } else {
            cp16z(dst + SM_MAT, B);
        }
    }
}

template <int EPI>
__global__ __launch_bounds__(128) void gemm_mma(
    int M, int N, int K,
    const fp16* __restrict__ A, const fp16* __restrict__ B,
    const float* __restrict__ bias, const float* __restrict__ cs,
    const float* __restrict__ ct, int relu,
    float* __restrict__ C, fp16* __restrict__ C16)
{
    extern __shared__ char smem[];
    uint32_t sbase = smem_u32(smem);

    int tid  = threadIdx.x;
    int wid  = tid >> 5, lane = tid & 31;
    int warpM = wid & 1;      // 2 x 64 rows
    int warpN = wid >> 1;     // 2 x 64 cols
    int rowBase = blockIdx.y * 128;
    int colBase = blockIdx.x * 128;

    float acc[4][8][4];
#pragma unroll
    for (int mt = 0; mt < 4; mt++)
#pragma unroll
        for (int nt = 0; nt < 8; nt++)
#pragma unroll
            for (int t = 0; t < 4; t++) acc[mt][nt][t] = 0.f;

    int KC = K >> 5;
    gemm_load_stage(sbase, tid, rowBase, colBase, N, K, 0, A, B);
    cp_commit();
    gemm_load_stage(sbase + SM_STAGE, tid, rowBase, colBase, N, K, 1, A, B);
    cp_commit();

    // ldmatrix lane addressing (non-trans for both operands)
    int aRow = (lane & 15);
    int aKof = (lane >> 4) * 8;
    int bN   = (lane & 7) + ((lane >> 4) << 3);
    int bKof = ((lane >> 3) & 1) * 8;

    int stage = 0;
    for (int kc = 0; kc < KC; kc++) {
        uint32_t sb = sbase + stage * SM_STAGE;
        if (kc + 2 < KC) {
            int ns = stage + 2; if (ns >= 3) ns -= 3;
            gemm_load_stage(sbase + ns * SM_STAGE, tid, rowBase, colBase,
                            N, K, kc + 2, A, B);
            cp_commit();
            cp_wait<2>();
        } else if (kc + 1 < KC) {
            cp_wait<1>();
        } else {
            cp_wait<0>();
        }
        __syncthreads();

#pragma unroll
        for (int ks = 0; ks < 2; ks++) {
            uint32_t af[4][4];
#pragma unroll
            for (int mt = 0; mt < 4; mt++) {
                uint32_t addr = sb + (warpM * 64 + mt * 16 + aRow) * SM_STRIDE
                              + (ks * 16 + aKof) * 2;
                ldsm4(af[mt], addr);
            }
#pragma unroll
            for (int p = 0; p < 4; p++) {
                uint32_t addr = sb + SM_MAT
                              + (warpN * 64 + p * 16 + bN) * SM_STRIDE
                              + (ks * 16 + bKof) * 2;
                uint32_t rb[4];
                ldsm4(rb, addr);
                uint32_t b0[2] = {rb[0], rb[1]}, b1[2] = {rb[2], rb[3]};
#pragma unroll
                for (int mt = 0; mt < 4; mt++) {
                    mma16816(acc[mt][2 * p],     af[mt], b0);
                    mma16816(acc[mt][2 * p + 1], af[mt], b1);
                }
            }
        }
        __syncthreads();
        stage++; if (stage == 3) stage = 0;
    }

    // epilogue
    int lrow = lane >> 2, lcol = (lane & 3) * 2;
    if (EPI == 2) {
        // apply bn/relu, stage to smem, then coalesced BCHW write
        float* tile = (float*)smem;  // [128 rows(hw)][129 cols(c)]
#pragma unroll
        for (int mt = 0; mt < 4; mt++)
#pragma unroll
            for (int nt = 0; nt < 8; nt++) {
                int cl = warpN * 64 + nt * 8 + lcol;
                int c = colBase + cl;
                float cs0 = cs[c], cs1 = cs[c + 1];
                float ct0 = ct[c], ct1 = ct[c + 1];
#pragma unroll
                for (int h2 = 0; h2 < 2; h2++) {
                    int rl = warpM * 64 + mt * 16 + lrow + h2 * 8;
                    float v0 = fmaxf(acc[mt][nt][h2 * 2 + 0] * cs0 + ct0, 0.f);
                    float v1 = fmaxf(acc[mt][nt][h2 * 2 + 1] * cs1 + ct1, 0.f);
                    tile[rl * 129 + cl]     = v0;
                    tile[rl * 129 + cl + 1] = v1;
                }
            }
        __syncthreads();
        int b = rowBase >> 12;
        int hwBase = rowBase & (HW_N - 1);
#pragma unroll 8
        for (int it = 0; it < 128; it++) {
            int idx = tid + it * 128;
            int cl = idx >> 7, hwl = idx & 127;
            C[((size_t)b * N + colBase + cl) * HW_N + hwBase + hwl] = tile[hwl * 129 + cl];
        }
        return;
    }
    int r0base = rowBase + warpM * 64;
    int c0base = colBase + warpN * 64;
#pragma unroll
    for (int mt = 0; mt < 4; mt++) {
#pragma unroll
        for (int nt = 0; nt < 8; nt++) {
            int c = c0base + nt * 8 + lcol;
            if (c >= N) continue;
            float bia0 = bias ? bias[c] : 0.f, bia1 = bias ? bias[c + 1] : 0.f;
            float cs0 = cs ? cs[c] : 1.f, cs1 = cs ? cs[c + 1] : 1.f;
            float ct0 = cs ? ct[c] : 0.f, ct1 = cs ? ct[c + 1] : 0.f;
#pragma unroll
            for (int h2 = 0; h2 < 2; h2++) {
                int r = r0base + mt * 16 + lrow + h2 * 8;
                float v0 = acc[mt][nt][h2 * 2 + 0] + bia0;
                float v1 = acc[mt][nt][h2 * 2 + 1] + bia1;
                v0 = v0 * cs0 + ct0; v1 = v1 * cs1 + ct1;
                if (relu) { v0 = fmaxf(v0, 0.f); v1 = fmaxf(v1, 0.f); }
                if (EPI == 0) {
                    *(float2*)(C + (size_t)r * N + c) = make_float2(v0, v1);
                } else {
                    __half2 hv; hv.x = __float2half(v0); hv.y = __float2half(v1);
                    *(__half2*)(C16 + (size_t)r * N + c) = hv;
                }
            }
        }
    }
}

// ---------------- one-shot prep kernel (grid.y = job) ----------------
__device__ __forceinline__ void tconv(const float* in, int K, int N,
                                      fp16* o, int rowOff, int i) {
    int k = i / N, n = i % N;
    o[(size_t)(rowOff + n) * K + k] = __float2half(in[i]);
}

__global__ void prep_all(
    const float* __restrict__ bn1_g, const float* __restrict__ bn1_b,
    const float* __restrict__ bn1_m, const float* __restrict__ bn1_v,
    const float* __restrict__ bn2_g, const float* __restrict__ bn2_b,
    const float* __restrict__ bn2_m, const float* __restrict__ bn2_v,
    const float* __restrict__ W_in, const float* __restrict__ W_out,
    const float* __restrict__ Wval, const float* __restrict__ Wo,
    const float* __restrict__ W1,   const float* __restrict__ W2,
    const float* __restrict__ Woff, const float* __restrict__ Wattn,
    const float* __restrict__ boff, const float* __restrict__ battn,
    float* __restrict__ bn1s, float* __restrict__ bn1t,
    float* __restrict__ bn2s, float* __restrict__ bn2t,
    fp16* __restrict__ WinT, fp16* __restrict__ WoutT,
    fp16* __restrict__ WvT,  fp16* __restrict__ WoT,
    fp16* __restrict__ W1T,  fp16* __restrict__ W2T,
    fp16* __restrict__ faT,  float* __restrict__ fab)
{
    int job = blockIdx.y;
    int i = blockIdx.x * 256 + threadIdx.x;
    if (job == 0) {
        if (i < DM) {
            float sc = bn1_g[i] * rsqrtf(bn1_v[i] + EPSF);
            bn1s[i] = sc; bn1t[i] = bn1_b[i] - bn1_m[i] * sc;
        }
    } else if (job == 1) {
        if (i < C_IN) {
            float sc = bn2_g[i] * rsqrtf(bn2_v[i] + EPSF);
            bn2s[i] = sc; bn2t[i] = bn2_b[i] - bn2_m[i] * sc;
        }
    } else if (job == 2) {
        if (i < DM * C_IN) WinT[i] = __float2half(W_in[i]);
    } else if (job == 3) {
        if (i < C_IN * DM) WoutT[i] = __float2half(W_out[i]);
    } else if (job < 6) {
        int li = job - 4;
        if (i < DM * DM) tconv(Wval + (size_t)li * DM * DM, DM, DM,
                               WvT + (size_t)li * DM * DM, 0, i);
    } else if (job < 8) {
        int li = job - 6;
        if (i < DM * DM) tconv(Wo + (size_t)li * DM * DM, DM, DM,
                               WoT + (size_t)li * DM * DM, 0, i);
    } else if (job < 10) {
        int li = job - 8;
        if (i < DM * D_FF) tconv(W1 + (size_t)li * DM * D_FF, DM, D_FF,
                                 W1T + (size_t)li * D_FF * DM, 0, i);
    } else if (job < 12) {
        int li = job - 10;
        if (i < D_FF * DM) tconv(W2 + (size_t)li * D_FF * DM, D_FF, DM,
                                 W2T + (size_t)li * DM * D_FF, 0, i);
    } else {
        int li = job - 12;
        fp16* fh = faT + (size_t)li * 96 * DM;
        if (i < DM * 64) {
            tconv(Woff + (size_t)li * DM * 64, DM, 64, fh, 0, i);
        } else if (i < DM * 64 + DM * 32) {
            tconv(Wattn + (size_t)li * DM * 32, DM, 32, fh, 64, i - DM * 64);
        } else if (i < DM * 64 + DM * 32 + 96) {
            int j = i - (DM * 64 + DM * 32);
            fab[li * 96 + j] = (j < 64) ? boff[li * 64 + j] : battn[li * 32 + j - 64];
        }
    }
}

// x (B, C_IN, HW) fp32 -> xT (B*HW, C_IN) single fp16
__global__ void transpose_x(const float* __restrict__ x, fp16* __restrict__ xT) {
    __shared__ float tile[32][33];
    int b  = blockIdx.z;
    int c0 = blockIdx.y * 32;
    int w0 = blockIdx.x * 32;
    tile[threadIdx.y][threadIdx.x] =
        x[((size_t)b * C_IN + (c0 + threadIdx.y)) * HW_N + w0 + threadIdx.x];
    __syncthreads();
    float v = tile[threadIdx.x][threadIdx.y];
    size_t o = ((size_t)b * HW_N + (w0 + threadIdx.y)) * C_IN + c0 + threadIdx.x;
    xT[o] = __float2half(v);
}

// qe (HW, DM) fp32 -> fp16 (layer-0 fa GEMM input)
__global__ void conv_qe(const float* __restrict__ qe, fp16* __restrict__ qe16) {
    int idx = blockIdx.x * 256 + threadIdx.x;
    if (idx < HW_N * DM) qe16[idx] = __float2half(qe[idx]);
}

// deformable bilinear sampling with fused softmax: warp per (m, head), lane = channel
__global__ __launch_bounds__(256) void sample_k(
    const fp16* __restrict__ val, const float* __restrict__ fa, unsigned famask,
    fp16* __restrict__ out16)
{
    int gt   = blockIdx.x * 256 + threadIdx.x;
    int warp = gt >> 5;
    int lane = gt & 31;
    int m = warp >> 3;
    int h = warp & 7;
    int b  = m >> 12;
    int hw = m & 4095;
    int wq = hw & 63;
    int hq = hw >> 6;

    unsigned mfa = (unsigned)m & famask;
    const float* offp  = fa + (size_t)mfa * 96 + h * 8;
    const float* lp    = fa + (size_t)mfa * 96 + 64 + h * 4;

    // fused softmax over 4 logits
    float l0 = lp[0], l1 = lp[1], l2 = lp[2], l3 = lp[3];
    float mx = fmaxf(fmaxf(l0, l1), fmaxf(l2, l3));
    float e0 = expf(l0 - mx), e1 = expf(l1 - mx), e2 = expf(l2 - mx), e3 = expf(l3 - mx);
    float inv = 1.f / (e0 + e1 + e2 + e3);
    float aw[4] = {e0 * inv, e1 * inv, e2 * inv, e3 * inv};

    const fp16* vbase = val + (size_t)b * HW_N * DM + h * 32 + lane;

    float acc = 0.f;
#pragma unroll
    for (int p = 0; p < 4; p++) {
        float gx = (float)wq + offp[2 * p];
        float gy = (float)hq + offp[2 * p + 1];
        float x0f = floorf(gx), y0f = floorf(gy);
        float wx = gx - x0f, wy = gy - y0f;
        int x0 = (int)x0f, y0 = (int)y0f;
        bool xv0 = (x0 >= 0) && (x0 < 64);
        bool xv1 = (x0 + 1 >= 0) && (x0 + 1 < 64);
        bool yv0 = (y0 >= 0) && (y0 < 64);
        bool yv1 = (y0 + 1 >= 0) && (y0 + 1 < 64);
        float v00 = 0.f, v10 = 0.f, v01 = 0.f, v11 = 0.f;
        if (xv0 && yv0) v00 = __half2float(vbase[(size_t)(y0 * 64 + x0) * DM]);
        if (xv1 && yv0) v10 = __half2float(vbase[(size_t)(y0 * 64 + x0 + 1) * DM]);
        if (xv0 && yv1) v01 = __half2float(vbase[(size_t)((y0 + 1) * 64 + x0) * DM]);
        if (xv1 && yv1) v11 = __half2float(vbase[(size_t)((y0 + 1) * 64 + x0 + 1) * DM]);
        float s = v00 * (1.f - wx) * (1.f - wy) + v10 * wx * (1.f - wy)
                + v01 * (1.f - wx) * wy + v11 * wx * wy;
        acc = fmaf(aw[p], s, acc);
    }
    out16[(size_t)m * DM + h * 32 + lane] = __float2half(acc);
}

// residual add + layernorm: fp32 state + fp16 shadow for GEMM input.
// qsrc/qmask: first call reads broadcast qe (mask = HW*DM-1), later calls read q32.
__global__ __launch_bounds__(256) void add_ln(
    float* __restrict__ q32, fp16* __restrict__ q16,
    const float* __restrict__ qsrc, unsigned qmask,
    const fp16* __restrict__ d,
    const float* __restrict__ g, const float* __restrict__ b)
{
    __shared__ float sh[8];
    int row = blockIdx.x;
    int t = threadIdx.x;
    size_t idx = (size_t)row * DM + t;
    float v = qsrc[idx & qmask] + __half2float(d[idx]);

    float s = v;
#pragma unroll
    for (int o = 16; o; o >>= 1) s += __shfl_down_sync(0xffffffffu, s, o);
    if ((t & 31) == 0) sh[t >> 5] = s;
    __syncthreads();
    float mean = 0.f;
#pragma unroll
    for (int w = 0; w < 8; w++) mean += sh[w];
    mean *= (1.f / 256.f);
    __syncthreads();

    float dv = v - mean;
    float s2 = dv * dv;
#pragma unroll
    for (int o = 16; o; o >>= 1) s2 += __shfl_down_sync(0xffffffffu, s2, o);
    if ((t & 31) == 0) sh[t >> 5] = s2;
    __syncthreads();
    float var = 0.f;
#pragma unroll
    for (int w = 0; w < 8; w++) var += sh[w];
    var *= (1.f / 256.f);

    float out = dv * rsqrtf(var + EPSF) * g[t] + b[t];
    q32[idx] = out;
    q16[idx] = __float2half(out);
}

// ---------------- launch ----------------
extern "C" void kernel_launch(void* const* d_in, const int* in_sizes, int n_in,
                              void* d_out, int out_size) {
    const float* x      = (const float*)d_in[0];
    const float* W_in   = (const float*)d_in[1];
    const float* bn1_g  = (const float*)d_in[2];
    const float* bn1_b  = (const float*)d_in[3];
    const float* bn1_m  = (const float*)d_in[4];
    const float* bn1_v  = (const float*)d_in[5];
    const float* qe     = (const float*)d_in[6];
    const float* Woff   = (const float*)d_in[7];
    const float* boff   = (const float*)d_in[8];
    const float* Wattn  = (const float*)d_in[9];
    const float* battn  = (const float*)d_in[10];
    const float* Wval   = (const float*)d_in[11];
    const float* bval   = (const float*)d_in[12];
    const float* Wo     = (const float*)d_in[13];
    const float* bo     = (const float*)d_in[14];
    const float* ln1_g  = (const float*)d_in[15];
    const float* ln1_b  = (const float*)d_in[16];
    const float* W1     = (const float*)d_in[17];
    const float* b1     = (const float*)d_in[18];
    const float* W2     = (const float*)d_in[19];
    const float* b2     = (const float*)d_in[20];
    const float* ln2_g  = (const float*)d_in[21];
    const float* ln2_b  = (const float*)d_in[22];
    const float* W_out  = (const float*)d_in[23];
    const float* bn2_g  = (const float*)d_in[24];
    const float* bn2_b  = (const float*)d_in[25];
    const float* bn2_m  = (const float*)d_in[26];
    const float* bn2_v  = (const float*)d_in[27];

    fp16 *xT16, *src16, *q16, *qe16, *val16, *samp16, *tmp16, *ffh16;
    fp16 *WinT, *WvT, *WoT, *W1T, *W2T, *faT, *WoutT;
    float *q32, *fa, *fab, *bn1s, *bn1t, *bn2s, *bn2t;
    cudaGetSymbolAddress((void**)&xT16, g_xT16);
    cudaGetSymbolAddress((void**)&src16, g_src16);
    cudaGetSymbolAddress((void**)&q32, g_q32);
    cudaGetSymbolAddress((void**)&q16, g_q16);
    cudaGetSymbolAddress((void**)&qe16, g_qe16);
    cudaGetSymbolAddress((void**)&val16, g_val16);
    cudaGetSymbolAddress((void**)&samp16, g_samp16);
    cudaGetSymbolAddress((void**)&tmp16, g_tmp16);
    cudaGetSymbolAddress((void**)&ffh16, g_ffh16);
    cudaGetSymbolAddress((void**)&fa, g_fa);   cudaGetSymbolAddress((void**)&fab, g_fab);
    cudaGetSymbolAddress((void**)&WinT, g_WinT);
    cudaGetSymbolAddress((void**)&WvT, g_WvT);
    cudaGetSymbolAddress((void**)&WoT, g_WoT);
    cudaGetSymbolAddress((void**)&W1T, g_W1T);
    cudaGetSymbolAddress((void**)&W2T, g_W2T);
    cudaGetSymbolAddress((void**)&faT, g_faT);
    cudaGetSymbolAddress((void**)&WoutT, g_WoutT);
    cudaGetSymbolAddress((void**)&bn1s, g_bn1s); cudaGetSymbolAddress((void**)&bn1t, g_bn1t);
    cudaGetSymbolAddress((void**)&bn2s, g_bn2s); cudaGetSymbolAddress((void**)&bn2t, g_bn2t);
    float* out = (float*)d_out;

    cudaFuncSetAttribute(gemm_mma<0>, cudaFuncAttributeMaxDynamicSharedMemorySize, GEMM_SMEM_BYTES);
    cudaFuncSetAttribute(gemm_mma<1>, cudaFuncAttributeMaxDynamicSharedMemorySize, GEMM_SMEM_BYTES);
    cudaFuncSetAttribute(gemm_mma<2>, cudaFuncAttributeMaxDynamicSharedMemorySize, GEMM_SMEM_BYTES);

    // 1: all weight/bn prep in one kernel
    prep_all<<<dim3(1024, 14), 256>>>(
        bn1_g, bn1_b, bn1_m, bn1_v, bn2_g, bn2_b, bn2_m, bn2_v,
        W_in, W_out, Wval, Wo, W1, W2, Woff, Wattn, boff, battn,
        bn1s, bn1t, bn2s, bn2t, WinT, WoutT, WvT, WoT, W1T, W2T, faT, fab);
    // 2
    transpose_x<<<dim3(128, 16, 8), dim3(32, 32)>>>(x, xT16);
    // 3 (tiny): qe -> fp16 for layer-0 fa GEMM
    conv_qe<<<(HW_N * DM) / 256, 256>>>(qe, qe16);
    // 4: proj_in -> src16 = relu(bn1( xT @ W_in^T ))
    gemm_mma<1><<<dim3(2, M_ROWS / 128), 128, GEMM_SMEM_BYTES>>>(
        M_ROWS, DM, C_IN, xT16, WinT,
        nullptr, bn1s, bn1t, 1, nullptr, src16);

    for (int i = 0; i < 2; i++) {
        size_t wo2 = (size_t)i * DM * DM;
        // fa GEMM: layer 0 exploits batch-broadcast q (M=4096, A = qe16)
        int Mfa = (i == 0) ? HW_N : M_ROWS;
        unsigned famask = (i == 0) ? 4095u : 0xFFFFFFFFu;
        const fp16* faA = (i == 0) ? qe16 : q16;
        gemm_mma<0><<<dim3(1, Mfa / 128), 128, GEMM_SMEM_BYTES>>>(
            Mfa, 96, DM, faA, faT + (size_t)i * 96 * DM,
            fab + i * 96, nullptr, nullptr, 0, fa, nullptr);
        // val16 = src @ Wval + bval (fp16 for sampler)
        gemm_mma<1><<<dim3(2, M_ROWS / 128), 128, GEMM_SMEM_BYTES>>>(
            M_ROWS, DM, DM, src16, WvT + wo2,
            bval + (size_t)i * DM, nullptr, nullptr, 0, nullptr, val16);
        sample_k<<<M_ROWS * 8 * 32 / 256, 256>>>(val16, fa, famask, samp16);
        // tmp16 = samp @ Wo + bo
        gemm_mma<1><<<dim3(2, M_ROWS / 128), 128, GEMM_SMEM_BYTES>>>(
            M_ROWS, DM, DM, samp16, WoT + wo2,
            bo + (size_t)i * DM, nullptr, nullptr, 0, nullptr, tmp16);
        // residual+LN; first one reads the qe broadcast directly
        if (i == 0)
            add_ln<<<M_ROWS, 256>>>(q32, q16, qe, (unsigned)(HW_N * DM - 1), tmp16,
                                    ln1_g, ln1_b);
        else
            add_ln<<<M_ROWS, 256>>>(q32, q16, q32, 0xFFFFFFFFu, tmp16,
                                    ln1_g + (size_t)i * DM, ln1_b + (size_t)i * DM);
        // ffh16 = relu(q @ W1 + b1)
        gemm_mma<1><<<dim3(8, M_ROWS / 128), 128, GEMM_SMEM_BYTES>>>(
            M_ROWS, D_FF, DM, q16, W1T + (size_t)i * D_FF * DM,
            b1 + (size_t)i * D_FF, nullptr, nullptr, 1, nullptr, ffh16);
        // tmp16 = ffh @ W2 + b2
        gemm_mma<1><<<dim3(2, M_ROWS / 128), 128, GEMM_SMEM_BYTES>>>(
            M_ROWS, DM, D_FF, ffh16, W2T + (size_t)i * DM * D_FF,
            b2 + (size_t)i * DM, nullptr, nullptr, 0, nullptr, tmp16);
        add_ln<<<M_ROWS, 256>>>(q32, q16, q32, 0xFFFFFFFFu, tmp16,
                                ln2_g + (size_t)i * DM, ln2_b + (size_t)i * DM);
    }

    // proj_out: out = relu(bn2( q @ W_out^T )) in BCHW (smem-staged coalesced)
    gemm_mma<2><<<dim3(4, M_ROWS / 128), 128, GEMM_SMEM_BYTES>>>(
        M_ROWS, C_IN, DM, q16, WoutT,
        nullptr, bn2s, bn2t, 1, out, nullptr);
}

// round 16
// speedup vs baseline: 1.0981x; 1.0981x over previous
#include <cuda_runtime.h>
#include <cuda_fp16.h>
#include <math.h>
#include <stddef.h>
#include <stdint.h>

#define M_ROWS 32768      // B*HW
#define DM     256
#define C_IN   512
#define D_FF   1024
#define HW_N   4096
#define EPSF   1e-5f
typedef __half fp16;

// ---------------- scratch (static device arrays) ----------------
__device__ fp16  g_xT16 [(size_t)M_ROWS * C_IN];
__device__ fp16  g_src16[(size_t)M_ROWS * DM];
__device__ float g_q32  [(size_t)M_ROWS * DM];
__device__ fp16  g_q16  [(size_t)M_ROWS * DM];
__device__ fp16  g_qe16 [(size_t)HW_N * DM];
__device__ fp16  g_val16[(size_t)M_ROWS * DM];
__device__ fp16  g_samp16[(size_t)M_ROWS * DM];
__device__ fp16  g_tmp16[(size_t)M_ROWS * DM];
__device__ fp16  g_ffh16[(size_t)M_ROWS * D_FF];
__device__ float g_fa   [(size_t)M_ROWS * 96];
__device__ fp16  g_WinT [DM * C_IN];
__device__ fp16  g_WvT  [2 * DM * DM];
__device__ fp16  g_WoT  [2 * DM * DM];
__device__ fp16  g_W1T  [2 * D_FF * DM];
__device__ fp16  g_W2T  [2 * DM * D_FF];
__device__ fp16  g_faT  [2 * 96 * DM];
__device__ fp16  g_WoutT[C_IN * DM];
__device__ float g_fab[2 * 96];
__device__ float g_bn1s[DM], g_bn1t[DM];
__device__ float g_bn2s[C_IN], g_bn2t[C_IN];

// ---------------- helpers ----------------
__device__ __forceinline__ uint32_t smem_u32(const void* p) {
    uint32_t a;
    asm("{ .reg .u64 t; cvta.to.shared.u64 t, %1; cvt.u32.u64 %0, t; }" : "=r"(a) : "l"(p));
    return a;
}
__device__ __forceinline__ void cp16(uint32_t d, const void* s) {
    asm volatile("cp.async.cg.shared.global [%0], [%1], 16;" :: "r"(d), "l"(s));
}
__device__ __forceinline__ void cp16z(uint32_t d, const void* s) {
    asm volatile("cp.async.cg.shared.global [%0], [%1], 16, %2;" :: "r"(d), "l"(s), "r"(0));
}
__device__ __forceinline__ void cp_commit() {
    asm volatile("cp.async.commit_group;");
}
template <int N>
__device__ __forceinline__ void cp_wait() {
    asm volatile("cp.async.wait_group %0;" :: "n"(N));
}
__device__ __forceinline__ void ldsm4(uint32_t* r, uint32_t a) {
    asm volatile("ldmatrix.sync.aligned.m8n8.x4.shared.b16 {%0,%1,%2,%3}, [%4];"
                 : "=r"(r[0]), "=r"(r[1]), "=r"(r[2]), "=r"(r[3]) : "r"(a));
}
__device__ __forceinline__ void mma16816(float* c, const uint32_t* a, const uint32_t* b) {
    asm volatile(
        "mma.sync.aligned.m16n8k16.row.col.f32.f16.f16.f32 "
        "{%0,%1,%2,%3}, {%4,%5,%6,%7}, {%8,%9}, {%0,%1,%2,%3};"
        : "+f"(c[0]), "+f"(c[1]), "+f"(c[2]), "+f"(c[3])
        : "r"(a[0]), "r"(a[1]), "r"(a[2]), "r"(a[3]), "r"(b[0]), "r"(b[1]));
}

// ---------------- HMMA GEMM ----------------
// C(M,N) = epi( A(M,K) @ B^T ): single-pass fp16 A and B (W^T row-major N x K).
// 128x128 block tile, 128 threads (4 warps, 2x2 grid, 64x64 warp tile),
// BK=32, TWO-stage cp.async double buffer (R14 mainloop). 2 smem mats/stage.
// EPI 0: fp32 row-major (+bias). EPI 1: fp16 out (+bias/bn/relu). EPI 2: fp32 BCHW.
#define SM_STRIDE   80
#define SM_MAT      10240
#define SM_STAGE    20480
#define GEMM_SMEM_BYTES 66560   // max(2*SM_STAGE, 128*129*4)

__device__ __forceinline__ void gemm_load_stage(
    uint32_t sb, int tid, int rowBase, int colBase, int N, int K, int kc,
    const fp16* __restrict__ A, const fp16* __restrict__ B)
{
    int k0 = kc * 32;
#pragma unroll
    for (int j = 0; j < 4; j++) {
        int g = tid + j * 128;
        int row = g >> 2, k4 = g & 3;   // 512 quads: 128 rows x 4 k-groups
        uint32_t dst = sb + row * SM_STRIDE + k4 * 16;
        size_t ga = (size_t)(rowBase + row) * K + k0 + k4 * 8;
        cp16(dst, A + ga);
        int n = colBase + row;
        if (n < N) {
            size_t gb = (size_t)n * K + k0 + k4 * 8;
            cp16(dst + SM_MAT, B + gb);
        } else {
            cp16z(dst + SM_MAT, B);
        }
    }
}

template <int EPI>
__global__ __launch_bounds__(128) void gemm_mma(
    int M, int N, int K,
    const fp16* __restrict__ A, const fp16* __restrict__ B,
    const float* __restrict__ bias, const float* __restrict__ cs,
    const float* __restrict__ ct, int relu,
    float* __restrict__ C, fp16* __restrict__ C16)
{
    extern __shared__ char smem[];
    uint32_t sbase = smem_u32(smem);

    int tid  = threadIdx.x;
    int wid  = tid >> 5, lane = tid & 31;
    int warpM = wid & 1;      // 2 x 64 rows
    int warpN = wid >> 1;     // 2 x 64 cols
    int rowBase = blockIdx.y * 128;
    int colBase = blockIdx.x * 128;

    float acc[4][8][4];
#pragma unroll
    for (int mt = 0; mt < 4; mt++)
#pragma unroll
        for (int nt = 0; nt < 8; nt++)
#pragma unroll
            for (int t = 0; t < 4; t++) acc[mt][nt][t] = 0.f;

    int KC = K >> 5;
    gemm_load_stage(sbase, tid, rowBase, colBase, N, K, 0, A, B);
    cp_commit();

    // ldmatrix lane addressing (non-trans for both operands)
    int aRow = (lane & 15);
    int aKof = (lane >> 4) * 8;
    int bN   = (lane & 7) + ((lane >> 4) << 3);
    int bKof = ((lane >> 3) & 1) * 8;

    for (int kc = 0; kc < KC; kc++) {
        uint32_t sb = sbase + (kc & 1) * SM_STAGE;
        if (kc + 1 < KC) {
            gemm_load_stage(sbase + ((kc + 1) & 1) * SM_STAGE, tid, rowBase, colBase,
                            N, K, kc + 1, A, B);
            cp_commit();
            cp_wait<1>();
        } else {
            cp_wait<0>();
        }
        __syncthreads();

#pragma unroll
        for (int ks = 0; ks < 2; ks++) {
            uint32_t af[4][4];
#pragma unroll
            for (int mt = 0; mt < 4; mt++) {
                uint32_t addr = sb + (warpM * 64 + mt * 16 + aRow) * SM_STRIDE
                              + (ks * 16 + aKof) * 2;
                ldsm4(af[mt], addr);
            }
#pragma unroll
            for (int p = 0; p < 4; p++) {
                uint32_t addr = sb + SM_MAT
                              + (warpN * 64 + p * 16 + bN) * SM_STRIDE
                              + (ks * 16 + bKof) * 2;
                uint32_t rb[4];
                ldsm4(rb, addr);
                uint32_t b0[2] = {rb[0], rb[1]}, b1[2] = {rb[2], rb[3]};
#pragma unroll
                for (int mt = 0; mt < 4; mt++) {
                    mma16816(acc[mt][2 * p],     af[mt], b0);
                    mma16816(acc[mt][2 * p + 1], af[mt], b1);
                }
            }
        }
        __syncthreads();
    }

    // epilogue
    int lrow = lane >> 2, lcol = (lane & 3) * 2;
    if (EPI == 2) {
        // apply bn/relu, stage to smem, then coalesced BCHW write
        float* tile = (float*)smem;  // [128 rows(hw)][129 cols(c)]
#pragma unroll
        for (int mt = 0; mt < 4; mt++)
#pragma unroll
            for (int nt = 0; nt < 8; nt++) {
                int cl = warpN * 64 + nt * 8 + lcol;
                int c = colBase + cl;
                float cs0 = cs[c], cs1 = cs[c + 1];
                float ct0 = ct[c], ct1 = ct[c + 1];
#pragma unroll
                for (int h2 = 0; h2 < 2; h2++) {
                    int rl = warpM * 64 + mt * 16 + lrow + h2 * 8;
                    float v0 = fmaxf(acc[mt][nt][h2 * 2 + 0] * cs0 + ct0, 0.f);
                    float v1 = fmaxf(acc[mt][nt][h2 * 2 + 1] * cs1 + ct1, 0.f);
                    tile[rl * 129 + cl]     = v0;
                    tile[rl * 129 + cl + 1] = v1;
                }
            }
        __syncthreads();
        int b = rowBase >> 12;
        int hwBase = rowBase & (HW_N - 1);
#pragma unroll 8
        for (int it = 0; it < 128; it++) {
            int idx = tid + it * 128;
            int cl = idx >> 7, hwl = idx & 127;
            C[((size_t)b * N + colBase + cl) * HW_N + hwBase + hwl] = tile[hwl * 129 + cl];
        }
        return;
    }
    int r0base = rowBase + warpM * 64;
    int c0base = colBase + warpN * 64;
#pragma unroll
    for (int mt = 0; mt < 4; mt++) {
#pragma unroll
        for (int nt = 0; nt < 8; nt++) {
            int c = c0base + nt * 8 + lcol;
            if (c >= N) continue;
            float bia0 = bias ? bias[c] : 0.f, bia1 = bias ? bias[c + 1] : 0.f;
            float cs0 = cs ? cs[c] : 1.f, cs1 = cs ? cs[c + 1] : 1.f;
            float ct0 = cs ? ct[c] : 0.f, ct1 = cs ? ct[c + 1] : 0.f;
#pragma unroll
            for (int h2 = 0; h2 < 2; h2++) {
                int r = r0base + mt * 16 + lrow + h2 * 8;
                float v0 = acc[mt][nt][h2 * 2 + 0] + bia0;
                float v1 = acc[mt][nt][h2 * 2 + 1] + bia1;
                v0 = v0 * cs0 + ct0; v1 = v1 * cs1 + ct1;
                if (relu) { v0 = fmaxf(v0, 0.f); v1 = fmaxf(v1, 0.f); }
                if (EPI == 0) {
                    *(float2*)(C + (size_t)r * N + c) = make_float2(v0, v1);
                } else {
                    __half2 hv; hv.x = __float2half(v0); hv.y = __float2half(v1);
                    *(__half2*)(C16 + (size_t)r * N + c) = hv;
                }
            }
        }
    }
}

// ---------------- one-shot prep kernel (grid.y = job) ----------------
__device__ __forceinline__ void tconv(const float* in, int K, int N,
                                      fp16* o, int rowOff, int i) {
    int k = i / N, n = i % N;
    o[(size_t)(rowOff + n) * K + k] = __float2half(in[i]);
}

__global__ void prep_all(
    const float* __restrict__ bn1_g, const float* __restrict__ bn1_b,
    const float* __restrict__ bn1_m, const float* __restrict__ bn1_v,
    const float* __restrict__ bn2_g, const float* __restrict__ bn2_b,
    const float* __restrict__ bn2_m, const float* __restrict__ bn2_v,
    const float* __restrict__ W_in, const float* __restrict__ W_out,
    const float* __restrict__ Wval, const float* __restrict__ Wo,
    const float* __restrict__ W1,   const float* __restrict__ W2,
    const float* __restrict__ Woff, const float* __restrict__ Wattn,
    const float* __restrict__ boff, const float* __restrict__ battn,
    float* __restrict__ bn1s, float* __restrict__ bn1t,
    float* __restrict__ bn2s, float* __restrict__ bn2t,
    fp16* __restrict__ WinT, fp16* __restrict__ WoutT,
    fp16* __restrict__ WvT,  fp16* __restrict__ WoT,
    fp16* __restrict__ W1T,  fp16* __restrict__ W2T,
    fp16* __restrict__ faT,  float* __restrict__ fab)
{
    int job = blockIdx.y;
    int i = blockIdx.x * 256 + threadIdx.x;
    if (job == 0) {
        if (i < DM) {
            float sc = bn1_g[i] * rsqrtf(bn1_v[i] + EPSF);
            bn1s[i] = sc; bn1t[i] = bn1_b[i] - bn1_m[i] * sc;
        }
    } else if (job == 1) {
        if (i < C_IN) {
            float sc = bn2_g[i] * rsqrtf(bn2_v[i] + EPSF);
            bn2s[i] = sc; bn2t[i] = bn2_b[i] - bn2_m[i] * sc;
        }
    } else if (job == 2) {
        if (i < DM * C_IN) WinT[i] = __float2half(W_in[i]);
    } else if (job == 3) {
        if (i < C_IN * DM) WoutT[i] = __float2half(W_out[i]);
    } else if (job < 6) {
        int li = job - 4;
        if (i < DM * DM) tconv(Wval + (size_t)li * DM * DM, DM, DM,
                               WvT + (size_t)li * DM * DM, 0, i);
    } else if (job < 8) {
        int li = job - 6;
        if (i < DM * DM) tconv(Wo + (size_t)li * DM * DM, DM, DM,
                               WoT + (size_t)li * DM * DM, 0, i);
    } else if (job < 10) {
        int li = job - 8;
        if (i < DM * D_FF) tconv(W1 + (size_t)li * DM * D_FF, DM, D_FF,
                                 W1T + (size_t)li * D_FF * DM, 0, i);
    } else if (job < 12) {
        int li = job - 10;
        if (i < D_FF * DM) tconv(W2 + (size_t)li * D_FF * DM, D_FF, DM,
                                 W2T + (size_t)li * DM * D_FF, 0, i);
    } else {
        int li = job - 12;
        fp16* fh = faT + (size_t)li * 96 * DM;
        if (i < DM * 64) {
            tconv(Woff + (size_t)li * DM * 64, DM, 64, fh, 0, i);
        } else if (i < DM * 64 + DM * 32) {
            tconv(Wattn + (size_t)li * DM * 32, DM, 32, fh, 64, i - DM * 64);
        } else if (i < DM * 64 + DM * 32 + 96) {
            int j = i - (DM * 64 + DM * 32);
            fab[li * 96 + j] = (j < 64) ? boff[li * 64 + j] : battn[li * 32 + j - 64];
        }
    }
}

// x (B, C_IN, HW) fp32 -> xT (B*HW, C_IN) single fp16
__global__ void transpose_x(const float* __restrict__ x, fp16* __restrict__ xT) {
    __shared__ float tile[32][33];
    int b  = blockIdx.z;
    int c0 = blockIdx.y * 32;
    int w0 = blockIdx.x * 32;
    tile[threadIdx.y][threadIdx.x] =
        x[((size_t)b * C_IN + (c0 + threadIdx.y)) * HW_N + w0 + threadIdx.x];
    __syncthreads();
    float v = tile[threadIdx.x][threadIdx.y];
    size_t o = ((size_t)b * HW_N + (w0 + threadIdx.y)) * C_IN + c0 + threadIdx.x;
    xT[o] = __float2half(v);
}

// qe (HW, DM) fp32 -> fp16 (layer-0 fa GEMM input)
__global__ void conv_qe(const float* __restrict__ qe, fp16* __restrict__ qe16) {
    int idx = blockIdx.x * 256 + threadIdx.x;
    if (idx < HW_N * DM) qe16[idx] = __float2half(qe[idx]);
}

// deformable bilinear sampling with fused softmax: warp per (m, head), lane = channel
__global__ __launch_bounds__(256) void sample_k(
    const fp16* __restrict__ val, const float* __restrict__ fa, unsigned famask,
    fp16* __restrict__ out16)
{
    int gt   = blockIdx.x * 256 + threadIdx.x;
    int warp = gt >> 5;
    int lane = gt & 31;
    int m = warp >> 3;
    int h = warp & 7;
    int b  = m >> 12;
    int hw = m & 4095;
    int wq = hw & 63;
    int hq = hw >> 6;

    unsigned mfa = (unsigned)m & famask;
    const float* offp  = fa + (size_t)mfa * 96 + h * 8;
    const float* lp    = fa + (size_t)mfa * 96 + 64 + h * 4;

    // fused softmax over 4 logits
    float l0 = lp[0], l1 = lp[1], l2 = lp[2], l3 = lp[3];
    float mx = fmaxf(fmaxf(l0, l1), fmaxf(l2, l3));
    float e0 = expf(l0 - mx), e1 = expf(l1 - mx), e2 = expf(l2 - mx), e3 = expf(l3 - mx);
    float inv = 1.f / (e0 + e1 + e2 + e3);
    float aw[4] = {e0 * inv, e1 * inv, e2 * inv, e3 * inv};

    const fp16* vbase = val + (size_t)b * HW_N * DM + h * 32 + lane;

    float acc = 0.f;
#pragma unroll
    for (int p = 0; p < 4; p++) {
        float gx = (float)wq + offp[2 * p];
        float gy = (float)hq + offp[2 * p + 1];
        float x0f = floorf(gx), y0f = floorf(gy);
        float wx = gx - x0f, wy = gy - y0f;
        int x0 = (int)x0f, y0 = (int)y0f;
        bool xv0 = (x0 >= 0) && (x0 < 64);
        bool xv1 = (x0 + 1 >= 0) && (x0 + 1 < 64);
        bool yv0 = (y0 >= 0) && (y0 < 64);
        bool yv1 = (y0 + 1 >= 0) && (y0 + 1 < 64);
        float v00 = 0.f, v10 = 0.f, v01 = 0.f, v11 = 0.f;
        if (xv0 && yv0) v00 = __half2float(vbase[(size_t)(y0 * 64 + x0) * DM]);
        if (xv1 && yv0) v10 = __half2float(vbase[(size_t)(y0 * 64 + x0 + 1) * DM]);
        if (xv0 && yv1) v01 = __half2float(vbase[(size_t)((y0 + 1) * 64 + x0) * DM]);
        if (xv1 && yv1) v11 = __half2float(vbase[(size_t)((y0 + 1) * 64 + x0 + 1) * DM]);
        float s = v00 * (1.f - wx) * (1.f - wy) + v10 * wx * (1.f - wy)
                + v01 * (1.f - wx) * wy + v11 * wx * wy;
        acc = fmaf(aw[p], s, acc);
    }
    out16[(size_t)m * DM + h * 32 + lane] = __float2half(acc);
}

// residual add + layernorm: fp32 state + fp16 shadow for GEMM input.
// qsrc/qmask: first call reads broadcast qe (mask = HW*DM-1), later calls read q32.
__global__ __launch_bounds__(256) void add_ln(
    float* __restrict__ q32, fp16* __restrict__ q16,
    const float* __restrict__ qsrc, unsigned qmask,
    const fp16* __restrict__ d,
    const float* __restrict__ g, const float* __restrict__ b)
{
    __shared__ float sh[8];
    int row = blockIdx.x;
    int t = threadIdx.x;
    size_t idx = (size_t)row * DM + t;
    float v = qsrc[idx & qmask] + __half2float(d[idx]);

    float s = v;
#pragma unroll
    for (int o = 16; o; o >>= 1) s += __shfl_down_sync(0xffffffffu, s, o);
    if ((t & 31) == 0) sh[t >> 5] = s;
    __syncthreads();
    float mean = 0.f;
#pragma unroll
    for (int w = 0; w < 8; w++) mean += sh[w];
    mean *= (1.f / 256.f);
    __syncthreads();

    float dv = v - mean;
    float s2 = dv * dv;
#pragma unroll
    for (int o = 16; o; o >>= 1) s2 += __shfl_down_sync(0xffffffffu, s2, o);
    if ((t & 31) == 0) sh[t >> 5] = s2;
    __syncthreads();
    float var = 0.f;
#pragma unroll
    for (int w = 0; w < 8; w++) var += sh[w];
    var *= (1.f / 256.f);

    float out = dv * rsqrtf(var + EPSF) * g[t] + b[t];
    q32[idx] = out;
    q16[idx] = __float2half(out);
}

// ---------------- launch ----------------
extern "C" void kernel_launch(void* const* d_in, const int* in_sizes, int n_in,
                              void* d_out, int out_size) {
    const float* x      = (const float*)d_in[0];
    const float* W_in   = (const float*)d_in[1];
    const float* bn1_g  = (const float*)d_in[2];
    const float* bn1_b  = (const float*)d_in[3];
    const float* bn1_m  = (const float*)d_in[4];
    const float* bn1_v  = (const float*)d_in[5];
    const float* qe     = (const float*)d_in[6];
    const float* Woff   = (const float*)d_in[7];
    const float* boff   = (const float*)d_in[8];
    const float* Wattn  = (const float*)d_in[9];
    const float* battn  = (const float*)d_in[10];
    const float* Wval   = (const float*)d_in[11];
    const float* bval   = (const float*)d_in[12];
    const float* Wo     = (const float*)d_in[13];
    const float* bo     = (const float*)d_in[14];
    const float* ln1_g  = (const float*)d_in[15];
    const float* ln1_b  = (const float*)d_in[16];
    const float* W1     = (const float*)d_in[17];
    const float* b1     = (const float*)d_in[18];
    const float* W2     = (const float*)d_in[19];
    const float* b2     = (const float*)d_in[20];
    const float* ln2_g  = (const float*)d_in[21];
    const float* ln2_b  = (const float*)d_in[22];
    const float* W_out  = (const float*)d_in[23];
    const float* bn2_g  = (const float*)d_in[24];
    const float* bn2_b  = (const float*)d_in[25];
    const float* bn2_m  = (const float*)d_in[26];
    const float* bn2_v  = (const float*)d_in[27];

    fp16 *xT16, *src16, *q16, *qe16, *val16, *samp16, *tmp16, *ffh16;
    fp16 *WinT, *WvT, *WoT, *W1T, *W2T, *faT, *WoutT;
    float *q32, *fa, *fab, *bn1s, *bn1t, *bn2s, *bn2t;
    cudaGetSymbolAddress((void**)&xT16, g_xT16);
    cudaGetSymbolAddress((void**)&src16, g_src16);
    cudaGetSymbolAddress((void**)&q32, g_q32);
    cudaGetSymbolAddress((void**)&q16, g_q16);
    cudaGetSymbolAddress((void**)&qe16, g_qe16);
    cudaGetSymbolAddress((void**)&val16, g_val16);
    cudaGetSymbolAddress((void**)&samp16, g_samp16);
    cudaGetSymbolAddress((void**)&tmp16, g_tmp16);
    cudaGetSymbolAddress((void**)&ffh16, g_ffh16);
    cudaGetSymbolAddress((void**)&fa, g_fa);   cudaGetSymbolAddress((void**)&fab, g_fab);
    cudaGetSymbolAddress((void**)&WinT, g_WinT);
    cudaGetSymbolAddress((void**)&WvT, g_WvT);
    cudaGetSymbolAddress((void**)&WoT, g_WoT);
    cudaGetSymbolAddress((void**)&W1T, g_W1T);
    cudaGetSymbolAddress((void**)&W2T, g_W2T);
    cudaGetSymbolAddress((void**)&faT, g_faT);
    cudaGetSymbolAddress((void**)&WoutT, g_WoutT);
    cudaGetSymbolAddress((void**)&bn1s, g_bn1s); cudaGetSymbolAddress((void**)&bn1t, g_bn1t);
    cudaGetSymbolAddress((void**)&bn2s, g_bn2s); cudaGetSymbolAddress((void**)&bn2t, g_bn2t);
    float* out = (float*)d_out;

    cudaFuncSetAttribute(gemm_mma<0>, cudaFuncAttributeMaxDynamicSharedMemorySize, GEMM_SMEM_BYTES);
    cudaFuncSetAttribute(gemm_mma<1>, cudaFuncAttributeMaxDynamicSharedMemorySize, GEMM_SMEM_BYTES);
    cudaFuncSetAttribute(gemm_mma<2>, cudaFuncAttributeMaxDynamicSharedMemorySize, GEMM_SMEM_BYTES);

    // 1: all weight/bn prep in one kernel
    prep_all<<<dim3(1024, 14), 256>>>(
        bn1_g, bn1_b, bn1_m, bn1_v, bn2_g, bn2_b, bn2_m, bn2_v,
        W_in, W_out, Wval, Wo, W1, W2, Woff, Wattn, boff, battn,
        bn1s, bn1t, bn2s, bn2t, WinT, WoutT, WvT, WoT, W1T, W2T, faT, fab);
    // 2
    transpose_x<<<dim3(128, 16, 8), dim3(32, 32)>>>(x, xT16);
    // 3 (tiny): qe -> fp16 for layer-0 fa GEMM
    conv_qe<<<(HW_N * DM) / 256, 256>>>(qe, qe16);
    // 4: proj_in -> src16 = relu(bn1( xT @ W_in^T ))
    gemm_mma<1><<<dim3(2, M_ROWS / 128), 128, GEMM_SMEM_BYTES>>>(
        M_ROWS, DM, C_IN, xT16, WinT,
        nullptr, bn1s, bn1t, 1, nullptr, src16);

    for (int i = 0; i < 2; i++) {
        size_t wo2 = (size_t)i * DM * DM;
        // fa GEMM: layer 0 exploits batch-broadcast q (M=4096, A = qe16)
        int Mfa = (i == 0) ? HW_N : M_ROWS;
        unsigned famask = (i == 0) ? 4095u : 0xFFFFFFFFu;
        const fp16* faA = (i == 0) ? qe16 : q16;
        gemm_mma<0><<<dim3(1, Mfa / 128), 128, GEMM_SMEM_BYTES>>>(
            Mfa, 96, DM, faA, faT + (size_t)i * 96 * DM,
            fab + i * 96, nullptr, nullptr, 0, fa, nullptr);
        // val16 = src @ Wval + bval (fp16 for sampler)
        gemm_mma<1><<<dim3(2, M_ROWS / 128), 128, GEMM_SMEM_BYTES>>>(
            M_ROWS, DM, DM, src16, WvT + wo2,
            bval + (size_t)i * DM, nullptr, nullptr, 0, nullptr, val16);
        sample_k<<<M_ROWS * 8 * 32 / 256, 256>>>(val16, fa, famask, samp16);
        // tmp16 = samp @ Wo + bo
        gemm_mma<1><<<dim3(2, M_ROWS / 128), 128, GEMM_SMEM_BYTES>>>(
            M_ROWS, DM, DM, samp16, WoT + wo2,
            bo + (size_t)i * DM, nullptr, nullptr, 0, nullptr, tmp16);
        // residual+LN; first one reads the qe broadcast directly
        if (i == 0)
            add_ln<<<M_ROWS, 256>>>(q32, q16, qe, (unsigned)(HW_N * DM - 1), tmp16,
                                    ln1_g, ln1_b);
        else
            add_ln<<<M_ROWS, 256>>>(q32, q16, q32, 0xFFFFFFFFu, tmp16,
                                    ln1_g + (size_t)i * DM, ln1_b + (size_t)i * DM);
        // ffh16 = relu(q @ W1 + b1)
        gemm_mma<1><<<dim3(8, M_ROWS / 128), 128, GEMM_SMEM_BYTES>>>(
            M_ROWS, D_FF, DM, q16, W1T + (size_t)i * D_FF * DM,
            b1 + (size_t)i * D_FF, nullptr, nullptr, 1, nullptr, ffh16);
        // tmp16 = ffh @ W2 + b2
        gemm_mma<1><<<dim3(2, M_ROWS / 128), 128, GEMM_SMEM_BYTES>>>(
            M_ROWS, DM, D_FF, ffh16, W2T + (size_t)i * DM * D_FF,
            b2 + (size_t)i * DM, nullptr, nullptr, 0, nullptr, tmp16);
        add_ln<<<M_ROWS, 256>>>(q32, q16, q32, 0xFFFFFFFFu, tmp16,
                                ln2_g + (size_t)i * DM, ln2_b + (size_t)i * DM);
    }

    // proj_out: out = relu(bn2( q @ W_out^T )) in BCHW (smem-staged coalesced)
    gemm_mma<2><<<dim3(4, M_ROWS / 128), 128, GEMM_SMEM_BYTES>>>(
        M_ROWS, C_IN, DM, q16, WoutT,
        nullptr, bn2s, bn2t, 1, out, nullptr);
}

// round 17
// speedup vs baseline: 1.1636x; 1.0597x over previous
#include <cuda_runtime.h>
#include <cuda_fp16.h>
#include <math.h>
#include <stddef.h>
#include <stdint.h>

#define M_ROWS 32768      // B*HW
#define DM     256
#define C_IN   512
#define D_FF   1024
#define HW_N   4096
#define EPSF   1e-5f
typedef __half fp16;

// ---------------- scratch (static device arrays) ----------------
__device__ fp16  g_xT16 [(size_t)M_ROWS * C_IN];
__device__ fp16  g_src16[(size_t)M_ROWS * DM];
__device__ float g_q32  [(size_t)M_ROWS * DM];
__device__ fp16  g_q16  [(size_t)M_ROWS * DM];
__device__ fp16  g_qe16 [(size_t)HW_N * DM];
__device__ fp16  g_val16[(size_t)M_ROWS * DM];
__device__ fp16  g_samp16[(size_t)M_ROWS * DM];
__device__ fp16  g_ffh16[(size_t)M_ROWS * D_FF];
__device__ float g_fa   [(size_t)M_ROWS * 96];
__device__ fp16  g_WinT [DM * C_IN];
__device__ fp16  g_WvT  [2 * DM * DM];
__device__ fp16  g_WoT  [2 * DM * DM];
__device__ fp16  g_W1T  [2 * D_FF * DM];
__device__ fp16  g_W2T  [2 * DM * D_FF];
__device__ fp16  g_faT  [2 * 96 * DM];
__device__ fp16  g_WoutT[C_IN * DM];
__device__ float g_fab[2 * 96];
__device__ float g_bn1s[DM], g_bn1t[DM];
__device__ float g_bn2s[C_IN], g_bn2t[C_IN];

// ---------------- helpers ----------------
__device__ __forceinline__ uint32_t smem_u32(const void* p) {
    uint32_t a;
    asm("{ .reg .u64 t; cvta.to.shared.u64 t, %1; cvt.u32.u64 %0, t; }" : "=r"(a) : "l"(p));
    return a;
}
__device__ __forceinline__ void cp16(uint32_t d, const void* s) {
    asm volatile("cp.async.cg.shared.global [%0], [%1], 16;" :: "r"(d), "l"(s));
}
__device__ __forceinline__ void cp16z(uint32_t d, const void* s) {
    asm volatile("cp.async.cg.shared.global [%0], [%1], 16, %2;" :: "r"(d), "l"(s), "r"(0));
}
__device__ __forceinline__ void cp_commit() {
    asm volatile("cp.async.commit_group;");
}
template <int N>
__device__ __forceinline__ void cp_wait() {
    asm volatile("cp.async.wait_group %0;" :: "n"(N));
}
__device__ __forceinline__ void ldsm4(uint32_t* r, uint32_t a) {
    asm volatile("ldmatrix.sync.aligned.m8n8.x4.shared.b16 {%0,%1,%2,%3}, [%4];"
                 : "=r"(r[0]), "=r"(r[1]), "=r"(r[2]), "=r"(r[3]) : "r"(a));
}
__device__ __forceinline__ void mma16816(float* c, const uint32_t* a, const uint32_t* b) {
    asm volatile(
        "mma.sync.aligned.m16n8k16.row.col.f32.f16.f16.f32 "
        "{%0,%1,%2,%3}, {%4,%5,%6,%7}, {%8,%9}, {%0,%1,%2,%3};"
        : "+f"(c[0]), "+f"(c[1]), "+f"(c[2]), "+f"(c[3])
        : "r"(a[0]), "r"(a[1]), "r"(a[2]), "r"(a[3]), "r"(b[0]), "r"(b[1]));
}

// ---------------- HMMA GEMM (generic, unchanged from R16) ----------------
#define SM_STRIDE   80
#define SM_MAT      10240
#define SM_STAGE    20480
#define GEMM_SMEM_BYTES 66560   // max(2*SM_STAGE, 128*129*4)

__device__ __forceinline__ void gemm_load_stage(
    uint32_t sb, int tid, int rowBase, int colBase, int N, int K, int kc,
    const fp16* __restrict__ A, const fp16* __restrict__ B)
{
    int k0 = kc * 32;
#pragma unroll
    for (int j = 0; j < 4; j++) {
        int g = tid + j * 128;
        int row = g >> 2, k4 = g & 3;   // 512 quads: 128 rows x 4 k-groups
        uint32_t dst = sb + row * SM_STRIDE + k4 * 16;
        size_t ga = (size_t)(rowBase + row) * K + k0 + k4 * 8;
        cp16(dst, A + ga);
        int n = colBase + row;
        if (n < N) {
            size_t gb = (size_t)n * K + k0 + k4 * 8;
            cp16(dst + SM_MAT, B + gb);
        } else {
            cp16z(dst + SM_MAT, B);
        }
    }
}

template <int EPI>
__global__ __launch_bounds__(128) void gemm_mma(
    int M, int N, int K,
    const fp16* __restrict__ A, const fp16* __restrict__ B,
    const float* __restrict__ bias, const float* __restrict__ cs,
    const float* __restrict__ ct, int relu,
    float* __restrict__ C, fp16* __restrict__ C16)
{
    extern __shared__ char smem[];
    uint32_t sbase = smem_u32(smem);

    int tid  = threadIdx.x;
    int wid  = tid >> 5, lane = tid & 31;
    int warpM = wid & 1;      // 2 x 64 rows
    int warpN = wid >> 1;     // 2 x 64 cols
    int rowBase = blockIdx.y * 128;
    int colBase = blockIdx.x * 128;

    float acc[4][8][4];
#pragma unroll
    for (int mt = 0; mt < 4; mt++)
#pragma unroll
        for (int nt = 0; nt < 8; nt++)
#pragma unroll
            for (int t = 0; t < 4; t++) acc[mt][nt][t] = 0.f;

    int KC = K >> 5;
    gemm_load_stage(sbase, tid, rowBase, colBase, N, K, 0, A, B);
    cp_commit();

    int aRow = (lane & 15);
    int aKof = (lane >> 4) * 8;
    int bN   = (lane & 7) + ((lane >> 4) << 3);
    int bKof = ((lane >> 3) & 1) * 8;

    for (int kc = 0; kc < KC; kc++) {
        uint32_t sb = sbase + (kc & 1) * SM_STAGE;
        if (kc + 1 < KC) {
            gemm_load_stage(sbase + ((kc + 1) & 1) * SM_STAGE, tid, rowBase, colBase,
                            N, K, kc + 1, A, B);
            cp_commit();
            cp_wait<1>();
        } else {
            cp_wait<0>();
        }
        __syncthreads();

#pragma unroll
        for (int ks = 0; ks < 2; ks++) {
            uint32_t af[4][4];
#pragma unroll
            for (int mt = 0; mt < 4; mt++) {
                uint32_t addr = sb + (warpM * 64 + mt * 16 + aRow) * SM_STRIDE
                              + (ks * 16 + aKof) * 2;
                ldsm4(af[mt], addr);
            }
#pragma unroll
            for (int p = 0; p < 4; p++) {
                uint32_t addr = sb + SM_MAT
                              + (warpN * 64 + p * 16 + bN) * SM_STRIDE
                              + (ks * 16 + bKof) * 2;
                uint32_t rb[4];
                ldsm4(rb, addr);
                uint32_t b0[2] = {rb[0], rb[1]}, b1[2] = {rb[2], rb[3]};
#pragma unroll
                for (int mt = 0; mt < 4; mt++) {
                    mma16816(acc[mt][2 * p],     af[mt], b0);
                    mma16816(acc[mt][2 * p + 1], af[mt], b1);
                }
            }
        }
        __syncthreads();
    }

    // epilogue
    int lrow = lane >> 2, lcol = (lane & 3) * 2;
    if (EPI == 2) {
        float* tile = (float*)smem;  // [128 rows(hw)][129 cols(c)]
#pragma unroll
        for (int mt = 0; mt < 4; mt++)
#pragma unroll
            for (int nt = 0; nt < 8; nt++) {
                int cl = warpN * 64 + nt * 8 + lcol;
                int c = colBase + cl;
                float cs0 = cs[c], cs1 = cs[c + 1];
                float ct0 = ct[c], ct1 = ct[c + 1];
#pragma unroll
                for (int h2 = 0; h2 < 2; h2++) {
                    int rl = warpM * 64 + mt * 16 + lrow + h2 * 8;
                    float v0 = fmaxf(acc[mt][nt][h2 * 2 + 0] * cs0 + ct0, 0.f);
                    float v1 = fmaxf(acc[mt][nt][h2 * 2 + 1] * cs1 + ct1, 0.f);
                    tile[rl * 129 + cl]     = v0;
                    tile[rl * 129 + cl + 1] = v1;
                }
            }
        __syncthreads();
        int b = rowBase >> 12;
        int hwBase = rowBase & (HW_N - 1);
#pragma unroll 8
        for (int it = 0; it < 128; it++) {
            int idx = tid + it * 128;
            int cl = idx >> 7, hwl = idx & 127;
            C[((size_t)b * N + colBase + cl) * HW_N + hwBase + hwl] = tile[hwl * 129 + cl];
        }
        return;
    }
    int r0base = rowBase + warpM * 64;
    int c0base = colBase + warpN * 64;
#pragma unroll
    for (int mt = 0; mt < 4; mt++) {
#pragma unroll
        for (int nt = 0; nt < 8; nt++) {
            int c = c0base + nt * 8 + lcol;
            if (c >= N) continue;
            float bia0 = bias ? bias[c] : 0.f, bia1 = bias ? bias[c + 1] : 0.f;
            float cs0 = cs ? cs[c] : 1.f, cs1 = cs ? cs[c + 1] : 1.f;
            float ct0 = cs ? ct[c] : 0.f, ct1 = cs ? ct[c + 1] : 0.f;
#pragma unroll
            for (int h2 = 0; h2 < 2; h2++) {
                int r = r0base + mt * 16 + lrow + h2 * 8;
                float v0 = acc[mt][nt][h2 * 2 + 0] + bia0;
                float v1 = acc[mt][nt][h2 * 2 + 1] + bia1;
                v0 = v0 * cs0 + ct0; v1 = v1 * cs1 + ct1;
                if (relu) { v0 = fmaxf(v0, 0.f); v1 = fmaxf(v1, 0.f); }
                if (EPI == 0) {
                    *(float2*)(C + (size_t)r * N + c) = make_float2(v0, v1);
                } else {
                    __half2 hv; hv.x = __float2half(v0); hv.y = __float2half(v1);
                    *(__half2*)(C16 + (size_t)r * N + c) = hv;
                }
            }
        }
    }
}

// ---------------- fused GEMM + residual + LayerNorm ----------------
// C(M,256) = LN( A(M,K) @ B^T + bias + residual ), N fixed = 256.
// 128x256 block tile, 256 threads (8 warps, 2x4 grid, 64x64 warp tiles).
// residual: qsrc[(r*256+c) & qmask] (qe broadcast for layer-0 LN1).
// Writes q32 (fp32 state) and q16 (fp16 shadow).
#define LN_SM_STAGE 30720   // A (10240) + B (256*80 = 20480)
#define GEMM_LN_SMEM_BYTES (2 * LN_SM_STAGE)

__device__ __forceinline__ void gemm_ln_load(
    uint32_t sb, int tid, int rowBase, int K, int kc,
    const fp16* __restrict__ A, const fp16* __restrict__ B)
{
    int k0 = kc * 32;
#pragma unroll
    for (int j = 0; j < 2; j++) {
        int g = tid + j * 256;
        int row = g >> 2, k4 = g & 3;
        cp16(sb + row * SM_STRIDE + k4 * 16,
             A + (size_t)(rowBase + row) * K + k0 + k4 * 8);
    }
#pragma unroll
    for (int j = 0; j < 4; j++) {
        int g = tid + j * 256;
        int row = g >> 2, k4 = g & 3;   // 0..255 (full N)
        cp16(sb + SM_MAT + row * SM_STRIDE + k4 * 16,
             B + (size_t)row * K + k0 + k4 * 8);
    }
}

__global__ __launch_bounds__(256) void gemm_ln(
    int K,
    const fp16* __restrict__ A, const fp16* __restrict__ B,
    const float* __restrict__ bias,
    const float* __restrict__ qsrc, unsigned qmask,
    const float* __restrict__ gw, const float* __restrict__ bw,
    float* __restrict__ q32, fp16* __restrict__ q16)
{
    extern __shared__ char smem[];
    uint32_t sbase = smem_u32(smem);

    int tid  = threadIdx.x;
    int wid  = tid >> 5, lane = tid & 31;
    int warpM = wid & 1;      // 2 x 64 rows
    int warpN = wid >> 1;     // 4 x 64 cols
    int rowBase = blockIdx.x * 128;

    float acc[4][8][4];
#pragma unroll
    for (int mt = 0; mt < 4; mt++)
#pragma unroll
        for (int nt = 0; nt < 8; nt++)
#pragma unroll
            for (int t = 0; t < 4; t++) acc[mt][nt][t] = 0.f;

    int KC = K >> 5;
    gemm_ln_load(sbase, tid, rowBase, K, 0, A, B);
    cp_commit();

    int aRow = (lane & 15);
    int aKof = (lane >> 4) * 8;
    int bN   = (lane & 7) + ((lane >> 4) << 3);
    int bKof = ((lane >> 3) & 1) * 8;

    for (int kc = 0; kc < KC; kc++) {
        uint32_t sb = sbase + (kc & 1) * LN_SM_STAGE;
        if (kc + 1 < KC) {
            gemm_ln_load(sbase + ((kc + 1) & 1) * LN_SM_STAGE, tid, rowBase, K,
                         kc + 1, A, B);
            cp_commit();
            cp_wait<1>();
        } else {
            cp_wait<0>();
        }
        __syncthreads();

#pragma unroll
        for (int ks = 0; ks < 2; ks++) {
            uint32_t af[4][4];
#pragma unroll
            for (int mt = 0; mt < 4; mt++) {
                uint32_t addr = sb + (warpM * 64 + mt * 16 + aRow) * SM_STRIDE
                              + (ks * 16 + aKof) * 2;
                ldsm4(af[mt], addr);
            }
#pragma unroll
            for (int p = 0; p < 4; p++) {
                uint32_t addr = sb + SM_MAT
                              + (warpN * 64 + p * 16 + bN) * SM_STRIDE
                              + (ks * 16 + bKof) * 2;
                uint32_t rb[4];
                ldsm4(rb, addr);
                uint32_t b0[2] = {rb[0], rb[1]}, b1[2] = {rb[2], rb[3]};
#pragma unroll
                for (int mt = 0; mt < 4; mt++) {
                    mma16816(acc[mt][2 * p],     af[mt], b0);
                    mma16816(acc[mt][2 * p + 1], af[mt], b1);
                }
            }
        }
        __syncthreads();
    }

    // ---- fused residual + LN epilogue ----
    int lrow = lane >> 2, lcol = (lane & 3) * 2;
    float s1[8], s2[8];
#pragma unroll
    for (int i = 0; i < 8; i++) { s1[i] = 0.f; s2[i] = 0.f; }
#pragma unroll
    for (int mt = 0; mt < 4; mt++) {
#pragma unroll
        for (int nt = 0; nt < 8; nt++) {
            int c = warpN * 64 + nt * 8 + lcol;
            float bia0 = bias[c], bia1 = bias[c + 1];
#pragma unroll
            for (int h2 = 0; h2 < 2; h2++) {
                int rl = warpM * 64 + mt * 16 + lrow + h2 * 8;
                unsigned rg = (unsigned)(rowBase + rl);
                unsigned qidx = (rg * 256u + (unsigned)c) & qmask;
                float2 qv = *(const float2*)(qsrc + qidx);
                float v0 = acc[mt][nt][h2 * 2 + 0] + bia0 + qv.x;
                float v1 = acc[mt][nt][h2 * 2 + 1] + bia1 + qv.y;
                acc[mt][nt][h2 * 2 + 0] = v0;
                acc[mt][nt][h2 * 2 + 1] = v1;
                s1[mt * 2 + h2] += v0 + v1;
                s2[mt * 2 + h2] += v0 * v0 + v1 * v1;
            }
        }
    }
#pragma unroll
    for (int i = 0; i < 8; i++) {
        s1[i] += __shfl_xor_sync(0xffffffffu, s1[i], 1);
        s1[i] += __shfl_xor_sync(0xffffffffu, s1[i], 2);
        s2[i] += __shfl_xor_sync(0xffffffffu, s2[i], 1);
        s2[i] += __shfl_xor_sync(0xffffffffu, s2[i], 2);
    }
    float* sm1 = (float*)smem;            // [128][4]
    float* sm2 = (float*)(smem + 2048);   // [128][4]
    if ((lane & 3) == 0) {
#pragma unroll
        for (int mt = 0; mt < 4; mt++)
#pragma unroll
            for (int h2 = 0; h2 < 2; h2++) {
                int rl = warpM * 64 + mt * 16 + lrow + h2 * 8;
                sm1[rl * 4 + warpN] = s1[mt * 2 + h2];
                sm2[rl * 4 + warpN] = s2[mt * 2 + h2];
            }
    }
    __syncthreads();
    float mean[8], rstd[8];
#pragma unroll
    for (int mt = 0; mt < 4; mt++)
#pragma unroll
        for (int h2 = 0; h2 < 2; h2++) {
            int rl = warpM * 64 + mt * 16 + lrow + h2 * 8;
            float S1 = sm1[rl * 4 + 0] + sm1[rl * 4 + 1]
                     + sm1[rl * 4 + 2] + sm1[rl * 4 + 3];
            float S2 = sm2[rl * 4 + 0] + sm2[rl * 4 + 1]
                     + sm2[rl * 4 + 2] + sm2[rl * 4 + 3];
            float mu = S1 * (1.f / 256.f);
            float var = S2 * (1.f / 256.f) - mu * mu;
            mean[mt * 2 + h2] = mu;
            rstd[mt * 2 + h2] = rsqrtf(var + EPSF);
        }
#pragma unroll
    for (int mt = 0; mt < 4; mt++) {
#pragma unroll
        for (int nt = 0; nt < 8; nt++) {
            int c = warpN * 64 + nt * 8 + lcol;
            float g0 = gw[c], g1 = gw[c + 1];
            float b0 = bw[c], b1 = bw[c + 1];
#pragma unroll
            for (int h2 = 0; h2 < 2; h2++) {
                int rl = warpM * 64 + mt * 16 + lrow + h2 * 8;
                size_t rg = (size_t)(rowBase + rl);
                float mu = mean[mt * 2 + h2], rs = rstd[mt * 2 + h2];
                float o0 = (acc[mt][nt][h2 * 2 + 0] - mu) * rs * g0 + b0;
                float o1 = (acc[mt][nt][h2 * 2 + 1] - mu) * rs * g1 + b1;
                *(float2*)(q32 + rg * 256 + c) = make_float2(o0, o1);
                __half2 hv; hv.x = __float2half(o0); hv.y = __float2half(o1);
                *(__half2*)(q16 + rg * 256 + c) = hv;
            }
        }
    }
}

// ---------------- one-shot prep kernel (grid.y = job) ----------------
__device__ __forceinline__ void tconv(const float* in, int K, int N,
                                      fp16* o, int rowOff, int i) {
    int k = i / N, n = i % N;
    o[(size_t)(rowOff + n) * K + k] = __float2half(in[i]);
}

__global__ void prep_all(
    const float* __restrict__ bn1_g, const float* __restrict__ bn1_b,
    const float* __restrict__ bn1_m, const float* __restrict__ bn1_v,
    const float* __restrict__ bn2_g, const float* __restrict__ bn2_b,
    const float* __restrict__ bn2_m, const float* __restrict__ bn2_v,
    const float* __restrict__ W_in, const float* __restrict__ W_out,
    const float* __restrict__ Wval, const float* __restrict__ Wo,
    const float* __restrict__ W1,   const float* __restrict__ W2,
    const float* __restrict__ Woff, const float* __restrict__ Wattn,
    const float* __restrict__ boff, const float* __restrict__ battn,
    float* __restrict__ bn1s, float* __restrict__ bn1t,
    float* __restrict__ bn2s, float* __restrict__ bn2t,
    fp16* __restrict__ WinT, fp16* __restrict__ WoutT,
    fp16* __restrict__ WvT,  fp16* __restrict__ WoT,
    fp16* __restrict__ W1T,  fp16* __restrict__ W2T,
    fp16* __restrict__ faT,  float* __restrict__ fab)
{
    int job = blockIdx.y;
    int i = blockIdx.x * 256 + threadIdx.x;
    if (job == 0) {
        if (i < DM) {
            float sc = bn1_g[i] * rsqrtf(bn1_v[i] + EPSF);
            bn1s[i] = sc; bn1t[i] = bn1_b[i] - bn1_m[i] * sc;
        }
    } else if (job == 1) {
        if (i < C_IN) {
            float sc = bn2_g[i] * rsqrtf(bn2_v[i] + EPSF);
            bn2s[i] = sc; bn2t[i] = bn2_b[i] - bn2_m[i] * sc;
        }
    } else if (job == 2) {
        if (i < DM * C_IN) WinT[i] = __float2half(W_in[i]);
    } else if (job == 3) {
        if (i < C_IN * DM) WoutT[i] = __float2half(W_out[i]);
    } else if (job < 6) {
        int li = job - 4;
        if (i < DM * DM) tconv(Wval + (size_t)li * DM * DM, DM, DM,
                               WvT + (size_t)li * DM * DM, 0, i);
    } else if (job < 8) {
        int li = job - 6;
        if (i < DM * DM) tconv(Wo + (size_t)li * DM * DM, DM, DM,
                               WoT + (size_t)li * DM * DM, 0, i);
    } else if (job < 10) {
        int li = job - 8;
        if (i < DM * D_FF) tconv(W1 + (size_t)li * DM * D_FF, DM, D_FF,
                                 W1T + (size_t)li * D_FF * DM, 0, i);
    } else if (job < 12) {
        int li = job - 10;
        if (i < D_FF * DM) tconv(W2 + (size_t)li * D_FF * DM, D_FF, DM,
                                 W2T + (size_t)li * DM * D_FF, 0, i);
    } else {
        int li = job - 12;
        fp16* fh = faT + (size_t)li * 96 * DM;
        if (i < DM * 64) {
            tconv(Woff + (size_t)li * DM * 64, DM, 64, fh, 0, i);
        } else if (i < DM * 64 + DM * 32) {
            tconv(Wattn + (size_t)li * DM * 32, DM, 32, fh, 64, i - DM * 64);
        } else if (i < DM * 64 + DM * 32 + 96) {
            int j = i - (DM * 64 + DM * 32);
            fab[li * 96 + j] = (j < 64) ? boff[li * 64 + j] : battn[li * 32 + j - 64];
        }
    }
}

// x (B, C_IN, HW) fp32 -> xT (B*HW, C_IN) single fp16
__global__ void transpose_x(const float* __restrict__ x, fp16* __restrict__ xT) {
    __shared__ float tile[32][33];
    int b  = blockIdx.z;
    int c0 = blockIdx.y * 32;
    int w0 = blockIdx.x * 32;
    tile[threadIdx.y][threadIdx.x] =
        x[((size_t)b * C_IN + (c0 + threadIdx.y)) * HW_N + w0 + threadIdx.x];
    __syncthreads();
    float v = tile[threadIdx.x][threadIdx.y];
    size_t o = ((size_t)b * HW_N + (w0 + threadIdx.y)) * C_IN + c0 + threadIdx.x;
    xT[o] = __float2half(v);
}

// qe (HW, DM) fp32 -> fp16 (layer-0 fa GEMM input)
__global__ void conv_qe(const float* __restrict__ qe, fp16* __restrict__ qe16) {
    int idx = blockIdx.x * 256 + threadIdx.x;
    if (idx < HW_N * DM) qe16[idx] = __float2half(qe[idx]);
}

// deformable bilinear sampling with fused softmax: warp per (m, head), lane = channel
__global__ __launch_bounds__(256) void sample_k(
    const fp16* __restrict__ val, const float* __restrict__ fa, unsigned famask,
    fp16* __restrict__ out16)
{
    int gt   = blockIdx.x * 256 + threadIdx.x;
    int warp = gt >> 5;
    int lane = gt & 31;
    int m = warp >> 3;
    int h = warp & 7;
    int b  = m >> 12;
    int hw = m & 4095;
    int wq = hw & 63;
    int hq = hw >> 6;

    unsigned mfa = (unsigned)m & famask;
    const float* offp  = fa + (size_t)mfa * 96 + h * 8;
    const float* lp    = fa + (size_t)mfa * 96 + 64 + h * 4;

    float l0 = lp[0], l1 = lp[1], l2 = lp[2], l3 = lp[3];
    float mx = fmaxf(fmaxf(l0, l1), fmaxf(l2, l3));
    float e0 = expf(l0 - mx), e1 = expf(l1 - mx), e2 = expf(l2 - mx), e3 = expf(l3 - mx);
    float inv = 1.f / (e0 + e1 + e2 + e3);
    float aw[4] = {e0 * inv, e1 * inv, e2 * inv, e3 * inv};

    const fp16* vbase = val + (size_t)b * HW_N * DM + h * 32 + lane;

    float acc = 0.f;
#pragma unroll
    for (int p = 0; p < 4; p++) {
        float gx = (float)wq + offp[2 * p];
        float gy = (float)hq + offp[2 * p + 1];
        float x0f = floorf(gx), y0f = floorf(gy);
        float wx = gx - x0f, wy = gy - y0f;
        int x0 = (int)x0f, y0 = (int)y0f;
        bool xv0 = (x0 >= 0) && (x0 < 64);
        bool xv1 = (x0 + 1 >= 0) && (x0 + 1 < 64);
        bool yv0 = (y0 >= 0) && (y0 < 64);
        bool yv1 = (y0 + 1 >= 0) && (y0 + 1 < 64);
        float v00 = 0.f, v10 = 0.f, v01 = 0.f, v11 = 0.f;
        if (xv0 && yv0) v00 = __half2float(vbase[(size_t)(y0 * 64 + x0) * DM]);
        if (xv1 && yv0) v10 = __half2float(vbase[(size_t)(y0 * 64 + x0 + 1) * DM]);
        if (xv0 && yv1) v01 = __half2float(vbase[(size_t)((y0 + 1) * 64 + x0) * DM]);
        if (xv1 && yv1) v11 = __half2float(vbase[(size_t)((y0 + 1) * 64 + x0 + 1) * DM]);
        float s = v00 * (1.f - wx) * (1.f - wy) + v10 * wx * (1.f - wy)
                + v01 * (1.f - wx) * wy + v11 * wx * wy;
        acc = fmaf(aw[p], s, acc);
    }
    out16[(size_t)m * DM + h * 32 + lane] = __float2half(acc);
}

// ---------------- launch ----------------
extern "C" void kernel_launch(void* const* d_in, const int* in_sizes, int n_in,
                              void* d_out, int out_size) {
    const float* x      = (const float*)d_in[0];
    const float* W_in   = (const float*)d_in[1];
    const float* bn1_g  = (const float*)d_in[2];
    const float* bn1_b  = (const float*)d_in[3];
    const float* bn1_m  = (const float*)d_in[4];
    const float* bn1_v  = (const float*)d_in[5];
    const float* qe     = (const float*)d_in[6];
    const float* Woff   = (const float*)d_in[7];
    const float* boff   = (const float*)d_in[8];
    const float* Wattn  = (const float*)d_in[9];
    const float* battn  = (const float*)d_in[10];
    const float* Wval   = (const float*)d_in[11];
    const float* bval   = (const float*)d_in[12];
    const float* Wo     = (const float*)d_in[13];
    const float* bo     = (const float*)d_in[14];
    const float* ln1_g  = (const float*)d_in[15];
    const float* ln1_b  = (const float*)d_in[16];
    const float* W1     = (const float*)d_in[17];
    const float* b1     = (const float*)d_in[18];
    const float* W2     = (const float*)d_in[19];
    const float* b2     = (const float*)d_in[20];
    const float* ln2_g  = (const float*)d_in[21];
    const float* ln2_b  = (const float*)d_in[22];
    const float* W_out  = (const float*)d_in[23];
    const float* bn2_g  = (const float*)d_in[24];
    const float* bn2_b  = (const float*)d_in[25];
    const float* bn2_m  = (const float*)d_in[26];
    const float* bn2_v  = (const float*)d_in[27];

    fp16 *xT16, *src16, *q16, *qe16, *val16, *samp16, *ffh16;
    fp16 *WinT, *WvT, *WoT, *W1T, *W2T, *faT, *WoutT;
    float *q32, *fa, *fab, *bn1s, *bn1t, *bn2s, *bn2t;
    cudaGetSymbolAddress((void**)&xT16, g_xT16);
    cudaGetSymbolAddress((void**)&src16, g_src16);
    cudaGetSymbolAddress((void**)&q32, g_q32);
    cudaGetSymbolAddress((void**)&q16, g_q16);
    cudaGetSymbolAddress((void**)&qe16, g_qe16);
    cudaGetSymbolAddress((void**)&val16, g_val16);
    cudaGetSymbolAddress((void**)&samp16, g_samp16);
    cudaGetSymbolAddress((void**)&ffh16, g_ffh16);
    cudaGetSymbolAddress((void**)&fa, g_fa);   cudaGetSymbolAddress((void**)&fab, g_fab);
    cudaGetSymbolAddress((void**)&WinT, g_WinT);
    cudaGetSymbolAddress((void**)&WvT, g_WvT);
    cudaGetSymbolAddress((void**)&WoT, g_WoT);
    cudaGetSymbolAddress((void**)&W1T, g_W1T);
    cudaGetSymbolAddress((void**)&W2T, g_W2T);
    cudaGetSymbolAddress((void**)&faT, g_faT);
    cudaGetSymbolAddress((void**)&WoutT, g_WoutT);
    cudaGetSymbolAddress((void**)&bn1s, g_bn1s); cudaGetSymbolAddress((void**)&bn1t, g_bn1t);
    cudaGetSymbolAddress((void**)&bn2s, g_bn2s); cudaGetSymbolAddress((void**)&bn2t, g_bn2t);
    float* out = (float*)d_out;

    cudaFuncSetAttribute(gemm_mma<0>, cudaFuncAttributeMaxDynamicSharedMemorySize, GEMM_SMEM_BYTES);
    cudaFuncSetAttribute(gemm_mma<1>, cudaFuncAttributeMaxDynamicSharedMemorySize, GEMM_SMEM_BYTES);
    cudaFuncSetAttribute(gemm_mma<2>, cudaFuncAttributeMaxDynamicSharedMemorySize, GEMM_SMEM_BYTES);
    cudaFuncSetAttribute(gemm_ln, cudaFuncAttributeMaxDynamicSharedMemorySize, GEMM_LN_SMEM_BYTES);

    // 1: all weight/bn prep in one kernel
    prep_all<<<dim3(1024, 14), 256>>>(
        bn1_g, bn1_b, bn1_m, bn1_v, bn2_g, bn2_b, bn2_m, bn2_v,
        W_in, W_out, Wval, Wo, W1, W2, Woff, Wattn, boff, battn,
        bn1s, bn1t, bn2s, bn2t, WinT, WoutT, WvT, WoT, W1T, W2T, faT, fab);
    // 2
    transpose_x<<<dim3(128, 16, 8), dim3(32, 32)>>>(x, xT16);
    // 3 (tiny): qe -> fp16 for layer-0 fa GEMM
    conv_qe<<<(HW_N * DM) / 256, 256>>>(qe, qe16);
    // 4: proj_in -> src16 = relu(bn1( xT @ W_in^T ))
    gemm_mma<1><<<dim3(2, M_ROWS / 128), 128, GEMM_SMEM_BYTES>>>(
        M_ROWS, DM, C_IN, xT16, WinT,
        nullptr, bn1s, bn1t, 1, nullptr, src16);

    for (int i = 0; i < 2; i++) {
        size_t wo2 = (size_t)i * DM * DM;
        // fa GEMM: layer 0 exploits batch-broadcast q (M=4096, A = qe16)
        int Mfa = (i == 0) ? HW_N : M_ROWS;
        unsigned famask = (i == 0) ? 4095u : 0xFFFFFFFFu;
        const fp16* faA = (i == 0) ? qe16 : q16;
        gemm_mma<0><<<dim3(1, Mfa / 128), 128, GEMM_SMEM_BYTES>>>(
            Mfa, 96, DM, faA, faT + (size_t)i * 96 * DM,
            fab + i * 96, nullptr, nullptr, 0, fa, nullptr);
        // val16 = src @ Wval + bval (fp16 for sampler)
        gemm_mma<1><<<dim3(2, M_ROWS / 128), 128, GEMM_SMEM_BYTES>>>(
            M_ROWS, DM, DM, src16, WvT + wo2,
            bval + (size_t)i * DM, nullptr, nullptr, 0, nullptr, val16);
        sample_k<<<M_ROWS * 8 * 32 / 256, 256>>>(val16, fa, famask, samp16);
        // fused: q = LN( samp @ Wo + bo + residual )
        if (i == 0)
            gemm_ln<<<M_ROWS / 128, 256, GEMM_LN_SMEM_BYTES>>>(
                DM, samp16, WoT + wo2, bo,
                qe, (unsigned)(HW_N * DM - 1), ln1_g, ln1_b, q32, q16);
        else
            gemm_ln<<<M_ROWS / 128, 256, GEMM_LN_SMEM_BYTES>>>(
                DM, samp16, WoT + wo2, bo + (size_t)i * DM,
                q32, 0xFFFFFFFFu, ln1_g + (size_t)i * DM, ln1_b + (size_t)i * DM,
                q32, q16);
        // ffh16 = relu(q @ W1 + b1)
        gemm_mma<1><<<dim3(8, M_ROWS / 128), 128, GEMM_SMEM_BYTES>>>(
            M_ROWS, D_FF, DM, q16, W1T + (size_t)i * D_FF * DM,
            b1 + (size_t)i * D_FF, nullptr, nullptr, 1, nullptr, ffh16);
        // fused: q = LN( ffh @ W2 + b2 + q )
        gemm_ln<<<M_ROWS / 128, 256, GEMM_LN_SMEM_BYTES>>>(
            D_FF, ffh16, W2T + (size_t)i * DM * D_FF, b2 + (size_t)i * DM,
            q32, 0xFFFFFFFFu, ln2_g + (size_t)i * DM, ln2_b + (size_t)i * DM,
            q32, q16);
    }

    // proj_out: out = relu(bn2( q @ W_out^T )) in BCHW (smem-staged coalesced)
    gemm_mma<2><<<dim3(4, M_ROWS / 128), 128, GEMM_SMEM_BYTES>>>(
        M_ROWS, C_IN, DM, q16, WoutT,
        nullptr, bn2s, bn2t, 1, out, nullptr);
}